// round 7
// baseline (speedup 1.0000x reference)
#include <cuda_runtime.h>
#include <cuda_bf16.h>

// Problem constants
#define Bc  32
#define Nc  1024
#define Tc  64
#define Dc  32
#define NTc 1088   // N + T

__device__ float g_sa[Bc * Nc * Dc];
__device__ float g_tb[Bc * Nc * Dc];
__device__ float g_sb[Bc * Tc * Dc];
__device__ float g_ta[Bc * Tc * Dc];

__device__ __forceinline__ float tanh_ap(float x) {
    float y;
    asm("tanh.approx.f32 %0, %1;" : "=f"(y) : "f"(x));
    return y;
}
__device__ __forceinline__ float tanh_relu(float x) {
    return tanh_ap(fmaxf(x, 0.0f));
}

// ---------------------------------------------------------------------------
// Kernel 1: projections (scaled by 0.5). 32 rows/block, weights staged once.
// ---------------------------------------------------------------------------
__global__ void __launch_bounds__(256)
proj_kernel(const float* __restrict__ sp, const float* __restrict__ tp,
            const float* __restrict__ st_w1, const float* __restrict__ st_b1,
            const float* __restrict__ ts_w1, const float* __restrict__ ts_b1)
{
    __shared__ float xs[32 * 33];
    __shared__ float wa[32 * 32];
    __shared__ float wb[32 * 32];

    int tid = threadIdx.y * 32 + threadIdx.x;
    int gr0 = blockIdx.x * 32;
    bool is_sp = gr0 < Bc * Nc;

    const float* src = is_sp ? (sp + (size_t)gr0 * Dc)
                             : (tp + (size_t)(gr0 - Bc * Nc) * Dc);
    for (int i = tid; i < 1024; i += 256)
        xs[(i >> 5) * 33 + (i & 31)] = src[i];
    for (int i = tid; i < 1024; i += 256) {
        int k = i >> 5, dd = i & 31;
        if (is_sp) {
            wa[i] = st_w1[k * 32 + dd];
            wb[i] = ts_w1[(32 + k) * 32 + dd];
        } else {
            wa[i] = st_w1[(32 + k) * 32 + dd];
            wb[i] = ts_w1[k * 32 + dd];
        }
    }
    __syncthreads();

    int d  = threadIdx.x;
    int ty = threadIdx.y;

    float acc1[4], acc2[4];
    float b1a = is_sp ? 0.f : st_b1[d];
    float b1b = is_sp ? 0.f : ts_b1[d];
    #pragma unroll
    for (int rr = 0; rr < 4; ++rr) { acc1[rr] = b1a; acc2[rr] = b1b; }

    #pragma unroll 4
    for (int k = 0; k < 32; ++k) {
        float wav = wa[k * 32 + d];
        float wbv = wb[k * 32 + d];
        #pragma unroll
        for (int rr = 0; rr < 4; ++rr) {
            float x = xs[(ty + 8 * rr) * 33 + k];
            acc1[rr] = fmaf(x, wav, acc1[rr]);
            acc2[rr] = fmaf(x, wbv, acc2[rr]);
        }
    }

    float* o1 = is_sp ? g_sa : g_sb;
    float* o2 = is_sp ? g_tb : g_ta;
    size_t base = is_sp ? (size_t)gr0 : (size_t)(gr0 - Bc * Nc);
    #pragma unroll
    for (int rr = 0; rr < 4; ++rr) {
        size_t r = base + ty + 8 * rr;
        o1[r * 32 + d] = 0.5f * acc1[rr];
        o2[r * 32 + d] = 0.5f * acc2[rr];
    }
}

// ---------------------------------------------------------------------------
// Fused kernel. 6432 blocks:
//   idx < 6400: period-25 interleave: r<17 -> gram 64x64 tile (4352 total,
//               upper triangle incl diag, mirrored), else pair (2048).
//   idx >= 6400: gram BR (32).
// ---------------------------------------------------------------------------
__global__ void __launch_bounds__(256, 4)
fused_kernel(const float* __restrict__ sp, const float* __restrict__ tp,
             const float* __restrict__ st_w2, const float* __restrict__ st_b2,
             const float* __restrict__ ts_w2, const float* __restrict__ ts_b2,
             float* __restrict__ out)
{
    __shared__ __align__(16) float sbuf[4800];   // 19.2 KB
    int idx = blockIdx.x;
    int tid = threadIdx.x;

    if (idx < 6400) {
        int q = idx / 25, r = idx % 25;

        if (r < 17) {
            // -------- gram TL: tanh(relu(S @ S^T)), 64x64 tile, packed dot --
            int g = q * 17 + r;         // 0..4351
            int b = g / 136, t = g % 136;
            int R = 0, rem = t;
            while (rem >= 16 - R) { rem -= 16 - R; ++R; }
            int C = R + rem;
            int r0 = R * 64, c0 = C * 64;
            bool mirror = (C > R);

            float* As = sbuf;           // [64][36] row-major
            float* Bs = sbuf + 2304;    // [64][36]
            float* BsP = mirror ? Bs : As;

            const float* Xb = sp + (size_t)b * Nc * Dc;
            // CF vectorized fill: chunk bin = (row + kq) mod 8, 4 per bin.
            for (int i = tid; i < 512; i += 256) {
                int row = i >> 3, kq = i & 7;
                *reinterpret_cast<float4*>(As + row * 36 + kq * 4) =
                    *reinterpret_cast<const float4*>(Xb + (size_t)(r0 + row) * 32 + kq * 4);
            }
            if (mirror) {
                for (int i = tid; i < 512; i += 256) {
                    int row = i >> 3, kq = i & 7;
                    *reinterpret_cast<float4*>(Bs + row * 36 + kq * 4) =
                        *reinterpret_cast<const float4*>(Xb + (size_t)(c0 + row) * 32 + kq * 4);
                }
            }
            __syncthreads();

            int tx = tid & 15;          // col group: cols tx + 16j
            int ty = tid >> 4;          // row group: rows ty + 16i

            unsigned as_u = (unsigned)__cvta_generic_to_shared(As) + ty * 144u;
            unsigned bs_u = (unsigned)__cvta_generic_to_shared(BsP) + tx * 144u;

            unsigned long long acc[4][4];
            #pragma unroll
            for (int i = 0; i < 4; ++i)
                #pragma unroll
                for (int j = 0; j < 4; ++j) acc[i][j] = 0ull;

            #pragma unroll 4
            for (int kq = 0; kq < 8; ++kq) {
                unsigned long long a01[4], a23[4];
                #pragma unroll
                for (int i = 0; i < 4; ++i)
                    asm("ld.shared.v2.b64 {%0,%1}, [%2];"
                        : "=l"(a01[i]), "=l"(a23[i])
                        : "r"(as_u + (unsigned)(i * 2304 + kq * 16)));
                #pragma unroll
                for (int h = 0; h < 2; ++h) {
                    unsigned long long b01[2], b23[2];
                    #pragma unroll
                    for (int jj = 0; jj < 2; ++jj)
                        asm("ld.shared.v2.b64 {%0,%1}, [%2];"
                            : "=l"(b01[jj]), "=l"(b23[jj])
                            : "r"(bs_u + (unsigned)((2 * h + jj) * 2304 + kq * 16)));
                    #pragma unroll
                    for (int i = 0; i < 4; ++i)
                        #pragma unroll
                        for (int jj = 0; jj < 2; ++jj) {
                            asm("fma.rn.f32x2 %0, %1, %2, %0;"
                                : "+l"(acc[i][2 * h + jj]) : "l"(a01[i]), "l"(b01[jj]));
                            asm("fma.rn.f32x2 %0, %1, %2, %0;"
                                : "+l"(acc[i][2 * h + jj]) : "l"(a23[i]), "l"(b23[jj]));
                        }
                }
            }

            // horizontal add + activation
            float val[4][4];
            #pragma unroll
            for (int i = 0; i < 4; ++i)
                #pragma unroll
                for (int j = 0; j < 4; ++j) {
                    float lo, hi;
                    asm("mov.b64 {%0, %1}, %2;" : "=f"(lo), "=f"(hi) : "l"(acc[i][j]));
                    val[i][j] = tanh_relu(lo + hi);
                }

            float* ob = out + (size_t)b * NTc * NTc;
            #pragma unroll
            for (int i = 0; i < 4; ++i)
                #pragma unroll
                for (int j = 0; j < 4; ++j)
                    ob[(size_t)(r0 + ty + 16 * i) * NTc + (c0 + tx + 16 * j)] = val[i][j];

            if (mirror) {
                __syncthreads();          // done reading As/Bs
                float* Ms = sbuf;         // [64][68]: Ms[col][row]
                #pragma unroll
                for (int i = 0; i < 4; ++i)
                    #pragma unroll
                    for (int j = 0; j < 4; ++j)
                        Ms[(tx + 16 * j) * 68 + (ty + 16 * i)] = val[i][j];
                __syncthreads();
                int c  = tid >> 2;        // 0..63 (mirror row = original col)
                int qd = tid & 3;
                #pragma unroll
                for (int u = 0; u < 4; ++u) {
                    float4 v = *reinterpret_cast<float4*>(Ms + c * 68 + qd * 16 + 4 * u);
                    *reinterpret_cast<float4*>(
                        ob + (size_t)(c0 + c) * NTc + r0 + qd * 16 + 4 * u) = v;
                }
            }
        } else {
            // ----------- bilinear MLP pair blocks: 32x64 tile ---------------
            int p = q * 8 + (r - 17);   // 0..2047
            int RA, CB, ROFF, COFF, r0, c0, b;
            const float *Arow, *Bcol, *w2, *b2;
            if (p < 1024) {            // st: rows spatial, cols temporal
                b = p >> 5; r0 = (p & 31) * 32; c0 = 0;
                RA = Nc; CB = Tc; ROFF = 0; COFF = Nc;
                Arow = g_sa; Bcol = g_sb; w2 = st_w2; b2 = st_b2;
            } else {                   // ts: rows temporal, cols spatial
                int s2 = p - 1024;
                b = s2 >> 5;
                int sub = s2 & 31;
                r0 = (sub & 1) * 32; c0 = (sub >> 1) * 64;
                RA = Tc; CB = Nc; ROFF = Nc; COFF = 0;
                Arow = g_ta; Bcol = g_tb; w2 = ts_w2; b2 = ts_b2;
            }

            float* rs  = sbuf;          // [32][36]
            float* cs  = sbuf + 1152;   // [64][36]
            float* w2s = sbuf + 3456;   // [32]
            float* wcp = sbuf + 3488;   // [1]

            for (int i = tid; i < 1024; i += 256)
                rs[(i >> 5) * 36 + (i & 31)] =
                    Arow[((size_t)b * RA + r0 + (i >> 5)) * 32 + (i & 31)];
            for (int i = tid; i < 2048; i += 256)
                cs[(i >> 5) * 36 + (i & 31)] =
                    Bcol[((size_t)b * CB + c0 + (i >> 5)) * 32 + (i & 31)];
            if (tid < 32) w2s[tid] = w2[tid];
            __syncthreads();
            if (tid == 0) {
                float s = 0.f;
                #pragma unroll
                for (int d = 0; d < 32; ++d) s += w2s[d];
                wcp[0] = fmaf(0.5f, s, b2[0]);
            }
            __syncthreads();

            int tc = tid & 63;
            int tr = tid >> 6;

            const float4* w2v = reinterpret_cast<const float4*>(w2s);
            const float4* cv4 = reinterpret_cast<const float4*>(cs + tc * 36);

            float acc[8];
            #pragma unroll
            for (int ii = 0; ii < 8; ++ii) acc[ii] = 0.f;

            #pragma unroll
            for (int dq = 0; dq < 8; ++dq) {
                float4 wv = w2v[dq];
                float4 cv = cv4[dq];
                #pragma unroll
                for (int ii = 0; ii < 8; ++ii) {
                    float4 rv = *reinterpret_cast<const float4*>(
                        rs + (tr + 4 * ii) * 36 + dq * 4);
                    float s;
                    s  = wv.x * tanh_ap(rv.x + cv.x);
                    s  = fmaf(wv.y, tanh_ap(rv.y + cv.y), s);
                    s  = fmaf(wv.z, tanh_ap(rv.z + cv.z), s);
                    s  = fmaf(wv.w, tanh_ap(rv.w + cv.w), s);
                    acc[ii] += s;
                }
            }

            float wconst = wcp[0];
            float* ob = out + (size_t)b * NTc * NTc;
            #pragma unroll
            for (int ii = 0; ii < 8; ++ii)
                ob[(size_t)(ROFF + r0 + tr + 4 * ii) * NTc + (COFF + c0 + tc)]
                    = tanh_relu(fmaf(0.5f, acc[ii], wconst));
        }
    } else {
        // ------------------- gram BR: tanh(relu(T @ T^T)) -------------------
        int b = idx - 6400;
        float* ts_s = sbuf;   // [64][33]
        const float* tb = tp + (size_t)b * Tc * Dc;
        for (int i = tid; i < 2048; i += 256)
            ts_s[(i >> 5) * 33 + (i & 31)] = tb[i];
        __syncthreads();

        float* ob = out + (size_t)b * NTc * NTc;
        for (int it = 0; it < 16; ++it) {
            int e = tid + 256 * it;
            int i = e >> 6, j = e & 63;
            float acc = 0.f;
            #pragma unroll
            for (int k = 0; k < 32; ++k)
                acc = fmaf(ts_s[i * 33 + k], ts_s[j * 33 + k], acc);
            ob[(size_t)(Nc + i) * NTc + (Nc + j)] = tanh_relu(acc);
        }
    }
}

// ---------------------------------------------------------------------------
extern "C" void kernel_launch(void* const* d_in, const int* in_sizes, int n_in,
                              void* d_out, int out_size)
{
    const float* sp    = (const float*)d_in[0];
    const float* tp    = (const float*)d_in[1];
    const float* st_w1 = (const float*)d_in[2];
    const float* st_b1 = (const float*)d_in[3];
    const float* st_w2 = (const float*)d_in[4];
    const float* st_b2 = (const float*)d_in[5];
    const float* ts_w1 = (const float*)d_in[6];
    const float* ts_b1 = (const float*)d_in[7];
    const float* ts_w2 = (const float*)d_in[8];
    const float* ts_b2 = (const float*)d_in[9];
    float* out = (float*)d_out;

    proj_kernel<<<dim3((Bc * (Nc + Tc)) / 32), dim3(32, 8)>>>(sp, tp, st_w1, st_b1, ts_w1, ts_b1);
    fused_kernel<<<6432, 256>>>(sp, tp, st_w2, st_b2, ts_w2, ts_b2, out);
}

// round 8
// speedup vs baseline: 1.0332x; 1.0332x over previous
#include <cuda_runtime.h>
#include <cuda_bf16.h>

// Problem constants
#define Bc  32
#define Nc  1024
#define Tc  64
#define Dc  32
#define NTc 1088   // N + T

__device__ float g_sa[Bc * Nc * Dc];
__device__ float g_tb[Bc * Nc * Dc];
__device__ float g_sb[Bc * Tc * Dc];
__device__ float g_ta[Bc * Tc * Dc];

__device__ __forceinline__ float tanh_ap(float x) {
    float y;
    asm("tanh.approx.f32 %0, %1;" : "=f"(y) : "f"(x));
    return y;
}
__device__ __forceinline__ float tanh_relu(float x) {
    return tanh_ap(fmaxf(x, 0.0f));
}

// tf32 hi/lo split: hi = rna(x), lo = rna(x - hi)
__device__ __forceinline__ void tf32_split(float x, unsigned& hi, unsigned& lo) {
    asm("cvt.rna.tf32.f32 %0, %1;" : "=r"(hi) : "f"(x));
    float lof = x - __uint_as_float(hi);
    asm("cvt.rna.tf32.f32 %0, %1;" : "=r"(lo) : "f"(lof));
}

__device__ __forceinline__ void mma_tf32(float* c, const unsigned* a,
                                         unsigned b0, unsigned b1) {
    asm("mma.sync.aligned.m16n8k8.row.col.f32.tf32.tf32.f32 "
        "{%0,%1,%2,%3}, {%4,%5,%6,%7}, {%8,%9}, {%0,%1,%2,%3};"
        : "+f"(c[0]), "+f"(c[1]), "+f"(c[2]), "+f"(c[3])
        : "r"(a[0]), "r"(a[1]), "r"(a[2]), "r"(a[3]), "r"(b0), "r"(b1));
}

// ---------------------------------------------------------------------------
// Kernel 1: projections (scaled by 0.5). 32 rows/block, weights staged once.
// ---------------------------------------------------------------------------
__global__ void __launch_bounds__(256)
proj_kernel(const float* __restrict__ sp, const float* __restrict__ tp,
            const float* __restrict__ st_w1, const float* __restrict__ st_b1,
            const float* __restrict__ ts_w1, const float* __restrict__ ts_b1)
{
    __shared__ float xs[32 * 33];
    __shared__ float wa[32 * 32];
    __shared__ float wb[32 * 32];

    int tid = threadIdx.y * 32 + threadIdx.x;
    int gr0 = blockIdx.x * 32;
    bool is_sp = gr0 < Bc * Nc;

    const float* src = is_sp ? (sp + (size_t)gr0 * Dc)
                             : (tp + (size_t)(gr0 - Bc * Nc) * Dc);
    for (int i = tid; i < 1024; i += 256)
        xs[(i >> 5) * 33 + (i & 31)] = src[i];
    for (int i = tid; i < 1024; i += 256) {
        int k = i >> 5, dd = i & 31;
        if (is_sp) {
            wa[i] = st_w1[k * 32 + dd];
            wb[i] = ts_w1[(32 + k) * 32 + dd];
        } else {
            wa[i] = st_w1[(32 + k) * 32 + dd];
            wb[i] = ts_w1[k * 32 + dd];
        }
    }
    __syncthreads();

    int d  = threadIdx.x;
    int ty = threadIdx.y;

    float acc1[4], acc2[4];
    float b1a = is_sp ? 0.f : st_b1[d];
    float b1b = is_sp ? 0.f : ts_b1[d];
    #pragma unroll
    for (int rr = 0; rr < 4; ++rr) { acc1[rr] = b1a; acc2[rr] = b1b; }

    #pragma unroll 4
    for (int k = 0; k < 32; ++k) {
        float wav = wa[k * 32 + d];
        float wbv = wb[k * 32 + d];
        #pragma unroll
        for (int rr = 0; rr < 4; ++rr) {
            float x = xs[(ty + 8 * rr) * 33 + k];
            acc1[rr] = fmaf(x, wav, acc1[rr]);
            acc2[rr] = fmaf(x, wbv, acc2[rr]);
        }
    }

    float* o1 = is_sp ? g_sa : g_sb;
    float* o2 = is_sp ? g_tb : g_ta;
    size_t base = is_sp ? (size_t)gr0 : (size_t)(gr0 - Bc * Nc);
    #pragma unroll
    for (int rr = 0; rr < 4; ++rr) {
        size_t r = base + ty + 8 * rr;
        o1[r * 32 + d] = 0.5f * acc1[rr];
        o2[r * 32 + d] = 0.5f * acc2[rr];
    }
}

// ---------------------------------------------------------------------------
// Fused kernel. 6432 blocks:
//   idx < 6400: period-25 interleave: r<17 -> gram 64x64 tile via tf32 MMA
//               (4352 total, upper triangle incl diag, mirrored), else pair.
//   idx >= 6400: gram BR (32).
// ---------------------------------------------------------------------------
__global__ void __launch_bounds__(256, 4)
fused_kernel(const float* __restrict__ sp, const float* __restrict__ tp,
             const float* __restrict__ st_w2, const float* __restrict__ st_b2,
             const float* __restrict__ ts_w2, const float* __restrict__ ts_b2,
             float* __restrict__ out)
{
    __shared__ __align__(16) float sbuf[4800];   // 19.2 KB
    int idx = blockIdx.x;
    int tid = threadIdx.x;

    if (idx < 6400) {
        int q = idx / 25, r = idx % 25;

        if (r < 17) {
            // -------- gram TL: tanh(relu(S @ S^T)), 64x64 tile, tf32 MMA ----
            int g = q * 17 + r;         // 0..4351
            int b = g / 136, t = g % 136;
            int R = 0, rem = t;
            while (rem >= 16 - R) { rem -= 16 - R; ++R; }
            int C = R + rem;
            int r0 = R * 64, c0 = C * 64;
            bool mirror = (C > R);

            float* As = sbuf;           // [64][36] row-major fp32
            float* Bs = sbuf + 2304;    // [64][36]
            float* BsP = mirror ? Bs : As;

            const float* Xb = sp + (size_t)b * Nc * Dc;
            for (int i = tid; i < 512; i += 256) {
                int row = i >> 3, kq = i & 7;
                *reinterpret_cast<float4*>(As + row * 36 + kq * 4) =
                    *reinterpret_cast<const float4*>(Xb + (size_t)(r0 + row) * 32 + kq * 4);
            }
            if (mirror) {
                for (int i = tid; i < 512; i += 256) {
                    int row = i >> 3, kq = i & 7;
                    *reinterpret_cast<float4*>(Bs + row * 36 + kq * 4) =
                        *reinterpret_cast<const float4*>(Xb + (size_t)(c0 + row) * 32 + kq * 4);
                }
            }
            __syncthreads();

            int w    = tid >> 5, lane = tid & 31;
            int wr   = w & 3;           // row quarter: rows 16wr..16wr+15
            int wc   = w >> 1 & 2 ? 0 : 0;  // placeholder (unused)
            int wcol = w >> 2;          // col half: cols 32wcol..+31
            (void)wc;
            int gg   = lane >> 2;       // groupID 0..7
            int tig  = lane & 3;        // thread-in-group 0..3

            const float* arow = As + (16 * wr + gg) * 36;

            float acc[4][4];
            #pragma unroll
            for (int nf = 0; nf < 4; ++nf)
                #pragma unroll
                for (int e = 0; e < 4; ++e) acc[nf][e] = 0.f;

            #pragma unroll
            for (int s = 0; s < 4; ++s) {
                int ks = 8 * s;
                // A fragment (m16 x k8): a0:(g,tig) a1:(g+8,tig) a2:(g,tig+4) a3:(g+8,tig+4)
                float ax[4];
                ax[0] = arow[ks + tig];
                ax[1] = arow[8 * 36 + ks + tig];
                ax[2] = arow[ks + tig + 4];
                ax[3] = arow[8 * 36 + ks + tig + 4];
                unsigned ahi[4], alo[4];
                #pragma unroll
                for (int e = 0; e < 4; ++e) tf32_split(ax[e], ahi[e], alo[e]);

                #pragma unroll
                for (int nf = 0; nf < 4; ++nf) {
                    // B fragment (k8 x n8, col-major): b0:(k=tig, n=g) b1:(k=tig+4, n=g)
                    const float* brow = BsP + (32 * wcol + 8 * nf + gg) * 36;
                    float bx0 = brow[ks + tig];
                    float bx1 = brow[ks + tig + 4];
                    unsigned bh0, bl0, bh1, bl1;
                    tf32_split(bx0, bh0, bl0);
                    tf32_split(bx1, bh1, bl1);
                    mma_tf32(acc[nf], ahi, bh0, bh1);   // hi*hi
                    mma_tf32(acc[nf], ahi, bl0, bl1);   // hi*lo
                    mma_tf32(acc[nf], alo, bh0, bh1);   // lo*hi
                }
            }

            // activation + direct store (C frag: c0:(g,2tig) c1:(g,2tig+1)
            //                                    c2:(g+8,2tig) c3:(g+8,2tig+1))
            float* ob = out + (size_t)b * NTc * NTc;
            int rowA = r0 + 16 * wr + gg;
            #pragma unroll
            for (int nf = 0; nf < 4; ++nf) {
                #pragma unroll
                for (int e = 0; e < 4; ++e) acc[nf][e] = tanh_relu(acc[nf][e]);
                int col = c0 + 32 * wcol + 8 * nf + 2 * tig;
                float2 p0; p0.x = acc[nf][0]; p0.y = acc[nf][1];
                float2 p1; p1.x = acc[nf][2]; p1.y = acc[nf][3];
                *reinterpret_cast<float2*>(ob + (size_t)rowA * NTc + col) = p0;
                *reinterpret_cast<float2*>(ob + (size_t)(rowA + 8) * NTc + col) = p1;
            }

            if (mirror) {
                __syncthreads();          // all warps done reading As/Bs
                float* Ms = sbuf;         // [64][68]: Ms[col_local][row_local]
                int rl = 16 * wr + gg;
                #pragma unroll
                for (int nf = 0; nf < 4; ++nf) {
                    int cl = 32 * wcol + 8 * nf + 2 * tig;
                    Ms[(cl    ) * 68 + rl    ] = acc[nf][0];
                    Ms[(cl + 1) * 68 + rl    ] = acc[nf][1];
                    Ms[(cl    ) * 68 + rl + 8] = acc[nf][2];
                    Ms[(cl + 1) * 68 + rl + 8] = acc[nf][3];
                }
                __syncthreads();
                int c  = tid >> 2;        // 0..63 (mirror row = original col)
                int qd = tid & 3;
                #pragma unroll
                for (int u = 0; u < 4; ++u) {
                    float4 v = *reinterpret_cast<float4*>(Ms + c * 68 + qd * 16 + 4 * u);
                    *reinterpret_cast<float4*>(
                        ob + (size_t)(c0 + c) * NTc + r0 + qd * 16 + 4 * u) = v;
                }
            }
        } else {
            // ----------- bilinear MLP pair blocks: 32x64 tile ---------------
            int p = q * 8 + (r - 17);   // 0..2047
            int RA, CB, ROFF, COFF, r0, c0, b;
            const float *Arow, *Bcol, *w2, *b2;
            if (p < 1024) {            // st: rows spatial, cols temporal
                b = p >> 5; r0 = (p & 31) * 32; c0 = 0;
                RA = Nc; CB = Tc; ROFF = 0; COFF = Nc;
                Arow = g_sa; Bcol = g_sb; w2 = st_w2; b2 = st_b2;
            } else {                   // ts: rows temporal, cols spatial
                int s2 = p - 1024;
                b = s2 >> 5;
                int sub = s2 & 31;
                r0 = (sub & 1) * 32; c0 = (sub >> 1) * 64;
                RA = Tc; CB = Nc; ROFF = Nc; COFF = 0;
                Arow = g_ta; Bcol = g_tb; w2 = ts_w2; b2 = ts_b2;
            }

            float* rs  = sbuf;          // [32][36]
            float* cs  = sbuf + 1152;   // [64][36]
            float* w2s = sbuf + 3456;   // [32]
            float* wcp = sbuf + 3488;   // [1]

            for (int i = tid; i < 1024; i += 256)
                rs[(i >> 5) * 36 + (i & 31)] =
                    Arow[((size_t)b * RA + r0 + (i >> 5)) * 32 + (i & 31)];
            for (int i = tid; i < 2048; i += 256)
                cs[(i >> 5) * 36 + (i & 31)] =
                    Bcol[((size_t)b * CB + c0 + (i >> 5)) * 32 + (i & 31)];
            if (tid < 32) w2s[tid] = w2[tid];
            __syncthreads();
            if (tid == 0) {
                float s = 0.f;
                #pragma unroll
                for (int d = 0; d < 32; ++d) s += w2s[d];
                wcp[0] = fmaf(0.5f, s, b2[0]);
            }
            __syncthreads();

            int tc = tid & 63;
            int tr = tid >> 6;

            const float4* w2v = reinterpret_cast<const float4*>(w2s);
            const float4* cv4 = reinterpret_cast<const float4*>(cs + tc * 36);

            float acc[8];
            #pragma unroll
            for (int ii = 0; ii < 8; ++ii) acc[ii] = 0.f;

            #pragma unroll
            for (int dq = 0; dq < 8; ++dq) {
                float4 wv = w2v[dq];
                float4 cv = cv4[dq];
                #pragma unroll
                for (int ii = 0; ii < 8; ++ii) {
                    float4 rv = *reinterpret_cast<const float4*>(
                        rs + (tr + 4 * ii) * 36 + dq * 4);
                    float s;
                    s  = wv.x * tanh_ap(rv.x + cv.x);
                    s  = fmaf(wv.y, tanh_ap(rv.y + cv.y), s);
                    s  = fmaf(wv.z, tanh_ap(rv.z + cv.z), s);
                    s  = fmaf(wv.w, tanh_ap(rv.w + cv.w), s);
                    acc[ii] += s;
                }
            }

            float wconst = wcp[0];
            float* ob = out + (size_t)b * NTc * NTc;
            #pragma unroll
            for (int ii = 0; ii < 8; ++ii)
                ob[(size_t)(ROFF + r0 + tr + 4 * ii) * NTc + (COFF + c0 + tc)]
                    = tanh_relu(fmaf(0.5f, acc[ii], wconst));
        }
    } else {
        // ------------------- gram BR: tanh(relu(T @ T^T)) -------------------
        int b = idx - 6400;
        float* ts_s = sbuf;   // [64][33]
        const float* tb = tp + (size_t)b * Tc * Dc;
        for (int i = tid; i < 2048; i += 256)
            ts_s[(i >> 5) * 33 + (i & 31)] = tb[i];
        __syncthreads();

        float* ob = out + (size_t)b * NTc * NTc;
        for (int it = 0; it < 16; ++it) {
            int e = tid + 256 * it;
            int i = e >> 6, j = e & 63;
            float acc = 0.f;
            #pragma unroll
            for (int k = 0; k < 32; ++k)
                acc = fmaf(ts_s[i * 33 + k], ts_s[j * 33 + k], acc);
            ob[(size_t)(Nc + i) * NTc + (Nc + j)] = tanh_relu(acc);
        }
    }
}

// ---------------------------------------------------------------------------
extern "C" void kernel_launch(void* const* d_in, const int* in_sizes, int n_in,
                              void* d_out, int out_size)
{
    const float* sp    = (const float*)d_in[0];
    const float* tp    = (const float*)d_in[1];
    const float* st_w1 = (const float*)d_in[2];
    const float* st_b1 = (const float*)d_in[3];
    const float* st_w2 = (const float*)d_in[4];
    const float* st_b2 = (const float*)d_in[5];
    const float* ts_w1 = (const float*)d_in[6];
    const float* ts_b1 = (const float*)d_in[7];
    const float* ts_w2 = (const float*)d_in[8];
    const float* ts_b2 = (const float*)d_in[9];
    float* out = (float*)d_out;

    proj_kernel<<<dim3((Bc * (Nc + Tc)) / 32), dim3(32, 8)>>>(sp, tp, st_w1, st_b1, ts_w1, ts_b1);
    fused_kernel<<<6432, 256>>>(sp, tp, st_w2, st_b2, ts_w2, ts_b2, out);
}

// round 9
// speedup vs baseline: 1.0838x; 1.0490x over previous
#include <cuda_runtime.h>
#include <cuda_bf16.h>

// Problem constants
#define Bc  32
#define Nc  1024
#define Tc  64
#define Dc  32
#define NTc 1088   // N + T

__device__ float g_sa[Bc * Nc * Dc];
__device__ float g_tb[Bc * Nc * Dc];
__device__ float g_sb[Bc * Tc * Dc];
__device__ float g_ta[Bc * Tc * Dc];

__device__ __forceinline__ float tanh_ap(float x) {
    float y;
    asm("tanh.approx.f32 %0, %1;" : "=f"(y) : "f"(x));
    return y;
}
__device__ __forceinline__ float tanh_relu(float x) {
    return tanh_ap(fmaxf(x, 0.0f));
}

__device__ __forceinline__ unsigned tf32_hi(float x) {
    unsigned h;
    asm("cvt.rna.tf32.f32 %0, %1;" : "=r"(h) : "f"(x));
    return h;
}

__device__ __forceinline__ void mma_tf32(float* c, const unsigned* a,
                                         unsigned b0, unsigned b1) {
    asm("mma.sync.aligned.m16n8k8.row.col.f32.tf32.tf32.f32 "
        "{%0,%1,%2,%3}, {%4,%5,%6,%7}, {%8,%9}, {%0,%1,%2,%3};"
        : "+f"(c[0]), "+f"(c[1]), "+f"(c[2]), "+f"(c[3])
        : "r"(a[0]), "r"(a[1]), "r"(a[2]), "r"(a[3]), "r"(b0), "r"(b1));
}

// ---------------------------------------------------------------------------
// Kernel 1: projections (scaled by 0.5). 272 blocks x 4 row-tiles; weights
// staged once per block (block is all-spatial or all-temporal).
// ---------------------------------------------------------------------------
__global__ void __launch_bounds__(256)
proj_kernel(const float* __restrict__ sp, const float* __restrict__ tp,
            const float* __restrict__ st_w1, const float* __restrict__ st_b1,
            const float* __restrict__ ts_w1, const float* __restrict__ ts_b1)
{
    __shared__ float xs[32 * 33];
    __shared__ float wa[32 * 32];
    __shared__ float wb[32 * 32];

    int tid = threadIdx.y * 32 + threadIdx.x;
    int tile0 = blockIdx.x * 4;
    bool is_sp = tile0 < 1024;         // 1024 spatial tiles, 64 temporal

    for (int i = tid; i < 1024; i += 256) {
        int k = i >> 5, dd = i & 31;
        if (is_sp) {
            wa[i] = st_w1[k * 32 + dd];
            wb[i] = ts_w1[(32 + k) * 32 + dd];
        } else {
            wa[i] = st_w1[(32 + k) * 32 + dd];
            wb[i] = ts_w1[k * 32 + dd];
        }
    }

    int d  = threadIdx.x;
    int ty = threadIdx.y;
    float b1a = is_sp ? 0.f : st_b1[d];
    float b1b = is_sp ? 0.f : ts_b1[d];

    float* o1 = is_sp ? g_sa : g_sb;
    float* o2 = is_sp ? g_tb : g_ta;

    for (int j = 0; j < 4; ++j) {
        int gr0 = (tile0 + j) * 32;
        const float* src = is_sp ? (sp + (size_t)gr0 * Dc)
                                 : (tp + (size_t)(gr0 - Bc * Nc) * Dc);
        __syncthreads();
        for (int i = tid; i < 1024; i += 256)
            xs[(i >> 5) * 33 + (i & 31)] = src[i];
        __syncthreads();

        float acc1[4], acc2[4];
        #pragma unroll
        for (int rr = 0; rr < 4; ++rr) { acc1[rr] = b1a; acc2[rr] = b1b; }

        #pragma unroll 4
        for (int k = 0; k < 32; ++k) {
            float wav = wa[k * 32 + d];
            float wbv = wb[k * 32 + d];
            #pragma unroll
            for (int rr = 0; rr < 4; ++rr) {
                float x = xs[(ty + 8 * rr) * 33 + k];
                acc1[rr] = fmaf(x, wav, acc1[rr]);
                acc2[rr] = fmaf(x, wbv, acc2[rr]);
            }
        }

        size_t base = is_sp ? (size_t)gr0 : (size_t)(gr0 - Bc * Nc);
        #pragma unroll
        for (int rr = 0; rr < 4; ++rr) {
            size_t rw = base + ty + 8 * rr;
            o1[rw * 32 + d] = 0.5f * acc1[rr];
            o2[rw * 32 + d] = 0.5f * acc2[rr];
        }
    }
}

// ---------------------------------------------------------------------------
// Fused kernel. 6432 blocks:
//   idx < 6400: period-25 interleave: r<17 -> gram 64x64 tile via tf32 MMA
//               (4352 total, upper triangle incl diag, mirrored), else pair.
//   idx >= 6400: gram BR (32).
// ---------------------------------------------------------------------------
__global__ void __launch_bounds__(256, 5)
fused_kernel(const float* __restrict__ sp, const float* __restrict__ tp,
             const float* __restrict__ st_w2, const float* __restrict__ st_b2,
             const float* __restrict__ ts_w2, const float* __restrict__ ts_b2,
             float* __restrict__ out)
{
    __shared__ __align__(16) float sbuf[4800];   // 19.2 KB
    int idx = blockIdx.x;
    int tid = threadIdx.x;

    if (idx < 6400) {
        int q = idx / 25, r = idx % 25;

        if (r < 17) {
            // -------- gram TL: tanh(relu(S @ S^T)), 64x64 tile, tf32 MMA ----
            int g = q * 17 + r;         // 0..4351
            int b = g / 136, t = g % 136;
            int R = 0, rem = t;
            while (rem >= 16 - R) { rem -= 16 - R; ++R; }
            int C = R + rem;
            int r0 = R * 64, c0 = C * 64;
            bool mirror = (C > R);

            float* As = sbuf;           // [64][36] row-major fp32
            float* Bs = sbuf + 2304;    // [64][36]
            float* BsP = mirror ? Bs : As;

            const float* Xb = sp + (size_t)b * Nc * Dc;
            for (int i = tid; i < 512; i += 256) {
                int row = i >> 3, kq = i & 7;
                *reinterpret_cast<float4*>(As + row * 36 + kq * 4) =
                    *reinterpret_cast<const float4*>(Xb + (size_t)(r0 + row) * 32 + kq * 4);
            }
            if (mirror) {
                for (int i = tid; i < 512; i += 256) {
                    int row = i >> 3, kq = i & 7;
                    *reinterpret_cast<float4*>(Bs + row * 36 + kq * 4) =
                        *reinterpret_cast<const float4*>(Xb + (size_t)(c0 + row) * 32 + kq * 4);
                }
            }
            __syncthreads();

            int w    = tid >> 5, lane = tid & 31;
            int wr   = w & 3;           // row quarter: rows 16wr..16wr+15
            int wcol = w >> 2;          // col half: cols 32wcol..+31
            int gg   = lane >> 2;       // groupID 0..7
            int tig  = lane & 3;        // thread-in-group 0..3

            const float* arow = As + (16 * wr + gg) * 36;

            float acc[4][4];
            #pragma unroll
            for (int nf = 0; nf < 4; ++nf)
                #pragma unroll
                for (int e = 0; e < 4; ++e) acc[nf][e] = 0.f;

            #pragma unroll
            for (int s = 0; s < 4; ++s) {
                int ks = 8 * s;
                unsigned ahi[4];
                ahi[0] = tf32_hi(arow[ks + tig]);
                ahi[1] = tf32_hi(arow[8 * 36 + ks + tig]);
                ahi[2] = tf32_hi(arow[ks + tig + 4]);
                ahi[3] = tf32_hi(arow[8 * 36 + ks + tig + 4]);

                #pragma unroll
                for (int nf = 0; nf < 4; ++nf) {
                    const float* brow = BsP + (32 * wcol + 8 * nf + gg) * 36;
                    unsigned bh0 = tf32_hi(brow[ks + tig]);
                    unsigned bh1 = tf32_hi(brow[ks + tig + 4]);
                    mma_tf32(acc[nf], ahi, bh0, bh1);
                }
            }

            // activation + direct store (C frag: c0:(g,2tig) c1:(g,2tig+1)
            //                                    c2:(g+8,2tig) c3:(g+8,2tig+1))
            float* ob = out + (size_t)b * NTc * NTc;
            int rowA = r0 + 16 * wr + gg;
            #pragma unroll
            for (int nf = 0; nf < 4; ++nf) {
                #pragma unroll
                for (int e = 0; e < 4; ++e) acc[nf][e] = tanh_relu(acc[nf][e]);
                int col = c0 + 32 * wcol + 8 * nf + 2 * tig;
                float2 p0; p0.x = acc[nf][0]; p0.y = acc[nf][1];
                float2 p1; p1.x = acc[nf][2]; p1.y = acc[nf][3];
                *reinterpret_cast<float2*>(ob + (size_t)rowA * NTc + col) = p0;
                *reinterpret_cast<float2*>(ob + (size_t)(rowA + 8) * NTc + col) = p1;
            }

            if (mirror) {
                __syncthreads();          // all warps done reading As/Bs
                float* Ms = sbuf;         // [64][68]: Ms[col_local][row_local]
                int rl = 16 * wr + gg;
                #pragma unroll
                for (int nf = 0; nf < 4; ++nf) {
                    int cl = 32 * wcol + 8 * nf + 2 * tig;
                    Ms[(cl    ) * 68 + rl    ] = acc[nf][0];
                    Ms[(cl + 1) * 68 + rl    ] = acc[nf][1];
                    Ms[(cl    ) * 68 + rl + 8] = acc[nf][2];
                    Ms[(cl + 1) * 68 + rl + 8] = acc[nf][3];
                }
                __syncthreads();
                int c  = tid >> 2;        // 0..63 (mirror row = original col)
                int qd = tid & 3;
                #pragma unroll
                for (int u = 0; u < 4; ++u) {
                    float4 v = *reinterpret_cast<float4*>(Ms + c * 68 + qd * 16 + 4 * u);
                    *reinterpret_cast<float4*>(
                        ob + (size_t)(c0 + c) * NTc + r0 + qd * 16 + 4 * u) = v;
                }
            }
        } else {
            // ----------- bilinear MLP pair blocks: 32x64 tile ---------------
            int p = q * 8 + (r - 17);   // 0..2047
            int RA, CB, ROFF, COFF, r0, c0, b;
            const float *Arow, *Bcol, *w2, *b2;
            if (p < 1024) {            // st: rows spatial, cols temporal
                b = p >> 5; r0 = (p & 31) * 32; c0 = 0;
                RA = Nc; CB = Tc; ROFF = 0; COFF = Nc;
                Arow = g_sa; Bcol = g_sb; w2 = st_w2; b2 = st_b2;
            } else {                   // ts: rows temporal, cols spatial
                int s2 = p - 1024;
                b = s2 >> 5;
                int sub = s2 & 31;
                r0 = (sub & 1) * 32; c0 = (sub >> 1) * 64;
                RA = Tc; CB = Nc; ROFF = Nc; COFF = 0;
                Arow = g_ta; Bcol = g_tb; w2 = ts_w2; b2 = ts_b2;
            }

            float* rs  = sbuf;          // [32][36]
            float* cs  = sbuf + 1152;   // [64][36]
            float* w2s = sbuf + 3456;   // [32]
            float* wcp = sbuf + 3488;   // [1]

            for (int i = tid; i < 1024; i += 256)
                rs[(i >> 5) * 36 + (i & 31)] =
                    Arow[((size_t)b * RA + r0 + (i >> 5)) * 32 + (i & 31)];
            for (int i = tid; i < 2048; i += 256)
                cs[(i >> 5) * 36 + (i & 31)] =
                    Bcol[((size_t)b * CB + c0 + (i >> 5)) * 32 + (i & 31)];
            if (tid < 32) w2s[tid] = w2[tid];
            __syncthreads();
            if (tid == 0) {
                float s = 0.f;
                #pragma unroll
                for (int d = 0; d < 32; ++d) s += w2s[d];
                wcp[0] = fmaf(0.5f, s, b2[0]);
            }
            __syncthreads();

            int tc = tid & 63;
            int tr = tid >> 6;

            const float4* w2v = reinterpret_cast<const float4*>(w2s);
            const float4* cv4 = reinterpret_cast<const float4*>(cs + tc * 36);

            float acc[8];
            #pragma unroll
            for (int ii = 0; ii < 8; ++ii) acc[ii] = 0.f;

            #pragma unroll
            for (int dq = 0; dq < 8; ++dq) {
                float4 wv = w2v[dq];
                float4 cv = cv4[dq];
                #pragma unroll
                for (int ii = 0; ii < 8; ++ii) {
                    float4 rv = *reinterpret_cast<const float4*>(
                        rs + (tr + 4 * ii) * 36 + dq * 4);
                    float s;
                    s  = wv.x * tanh_ap(rv.x + cv.x);
                    s  = fmaf(wv.y, tanh_ap(rv.y + cv.y), s);
                    s  = fmaf(wv.z, tanh_ap(rv.z + cv.z), s);
                    s  = fmaf(wv.w, tanh_ap(rv.w + cv.w), s);
                    acc[ii] += s;
                }
            }

            float wconst = wcp[0];
            float* ob = out + (size_t)b * NTc * NTc;
            #pragma unroll
            for (int ii = 0; ii < 8; ++ii)
                ob[(size_t)(ROFF + r0 + tr + 4 * ii) * NTc + (COFF + c0 + tc)]
                    = tanh_relu(fmaf(0.5f, acc[ii], wconst));
        }
    } else {
        // ------------------- gram BR: tanh(relu(T @ T^T)) -------------------
        int b = idx - 6400;
        float* ts_s = sbuf;   // [64][33]
        const float* tb = tp + (size_t)b * Tc * Dc;
        for (int i = tid; i < 2048; i += 256)
            ts_s[(i >> 5) * 33 + (i & 31)] = tb[i];
        __syncthreads();

        float* ob = out + (size_t)b * NTc * NTc;
        for (int it = 0; it < 16; ++it) {
            int e = tid + 256 * it;
            int i = e >> 6, j = e & 63;
            float acc = 0.f;
            #pragma unroll
            for (int k = 0; k < 32; ++k)
                acc = fmaf(ts_s[i * 33 + k], ts_s[j * 33 + k], acc);
            ob[(size_t)(Nc + i) * NTc + (Nc + j)] = tanh_relu(acc);
        }
    }
}

// ---------------------------------------------------------------------------
extern "C" void kernel_launch(void* const* d_in, const int* in_sizes, int n_in,
                              void* d_out, int out_size)
{
    const float* sp    = (const float*)d_in[0];
    const float* tp    = (const float*)d_in[1];
    const float* st_w1 = (const float*)d_in[2];
    const float* st_b1 = (const float*)d_in[3];
    const float* st_w2 = (const float*)d_in[4];
    const float* st_b2 = (const float*)d_in[5];
    const float* ts_w1 = (const float*)d_in[6];
    const float* ts_b1 = (const float*)d_in[7];
    const float* ts_w2 = (const float*)d_in[8];
    const float* ts_b2 = (const float*)d_in[9];
    float* out = (float*)d_out;

    proj_kernel<<<272, dim3(32, 8)>>>(sp, tp, st_w1, st_b1, ts_w1, ts_b1);
    fused_kernel<<<6432, 256>>>(sp, tp, st_w2, st_b2, ts_w2, ts_b2, out);
}